// round 10
// baseline (speedup 1.0000x reference)
#include <cuda_runtime.h>
#include <cuda_fp16.h>
#include <cstdint>

// ---------------------------------------------------------------------------
// Problem constants
// ---------------------------------------------------------------------------
#define Bn     32
#define Nn     2048
#define PDn    2
#define LATn   128
#define Hn     256
#define STEPSn 5
#define DINn   131
#define NPTS   (Bn * Nn)         // 65536
#define PPC    128               // points per CTA (= GEMM M)
#define NCTA   (NPTS / PPC)      // 512
#define KCH    32                // K-chunk
#define NCHUNK (Hn / KCH)        // 8
#define NTHREADS 256
#define TILES_PER_STEP 16        // 8 div (M) + 8 vel (W2hi+W2lo)
#define NTILES (STEPSn * TILES_PER_STEP)   // 80

// ---------------------------------------------------------------------------
// Device globals
// ---------------------------------------------------------------------------
// fp16 weights: [0]=W2hi, [1]=W2lo, [2]=M; each [8 chunk][256 j][32 k]
__device__ __align__(16) __half g_W16[3 * 65536];
__device__ __align__(16) float g_base[Bn * Hn];
__device__ __align__(16) float g_c0[Hn], g_c1[Hn], g_ct[Hn], g_csum[Hn];

__device__ __forceinline__ float ftanh(float x) {
    float e = __expf(2.0f * x);
    return 1.0f - __fdividef(2.0f, e + 1.0f);
}
__device__ __forceinline__ uint32_t smem_u32(const void* p) {
    uint32_t a;
    asm("{ .reg .u64 t; cvta.to.shared.u64 t, %1; cvt.u32.u64 %0, t; }"
        : "=r"(a) : "l"(p));
    return a;
}
__device__ __forceinline__ void ldsm4(uint32_t& r0, uint32_t& r1,
                                      uint32_t& r2, uint32_t& r3, uint32_t addr) {
    asm volatile("ldmatrix.sync.aligned.m8n8.x4.shared.b16 {%0,%1,%2,%3}, [%4];"
                 : "=r"(r0), "=r"(r1), "=r"(r2), "=r"(r3) : "r"(addr));
}
__device__ __forceinline__ void mma16816(float* d, const uint32_t* a,
                                         uint32_t b0, uint32_t b1) {
    asm volatile(
        "mma.sync.aligned.m16n8k16.row.col.f32.f16.f16.f32 "
        "{%0,%1,%2,%3},{%4,%5,%6,%7},{%8,%9},{%0,%1,%2,%3};"
        : "+f"(d[0]), "+f"(d[1]), "+f"(d[2]), "+f"(d[3])
        : "r"(a[0]), "r"(a[1]), "r"(a[2]), "r"(a[3]), "r"(b0), "r"(b1));
}
__device__ __forceinline__ void cp16(uint32_t dst, const void* src) {
    asm volatile("cp.async.cg.shared.global [%0], [%1], 16;"
                 :: "r"(dst), "l"(src));
}
#define CP_COMMIT() asm volatile("cp.async.commit_group;" ::: "memory")
#define CP_WAIT0()  asm volatile("cp.async.wait_group 0;" ::: "memory")

// ---------------------------------------------------------------------------
// Precompute 1: per-row W1 decomposition + per-batch base vectors
// ---------------------------------------------------------------------------
__global__ void precomp_aux(const float* __restrict__ W1,
                            const float* __restrict__ b1,
                            const float* __restrict__ z) {
    int k = threadIdx.x;
    int b = blockIdx.x;
    const float* row = W1 + k * DINn;
    float d = b1[k];
    const float* zb = z + b * LATn;
#pragma unroll 16
    for (int l = 0; l < LATn; ++l) d += row[3 + l] * zb[l];
    g_base[b * Hn + k] = d;
    if (b == 0) {
        float s = 0.f;
#pragma unroll 16
        for (int l = 0; l < LATn; ++l) s += row[3 + l];
        g_c0[k] = row[0]; g_c1[k] = row[1]; g_ct[k] = row[2]; g_csum[k] = s;
    }
}

// ---------------------------------------------------------------------------
// Precompute 2: W2 (hi/lo split) and fused divergence matrix M -> fp16
// ---------------------------------------------------------------------------
__global__ void precomp_w(const float* __restrict__ W1,
                          const float* __restrict__ W2,
                          const float* __restrict__ W3) {
    int j = blockIdx.x;   // 256
    int k = threadIdx.x;  // 256
    float w2 = W2[j * Hn + k];
    float mm = w2 * (W1[k * DINn] * W3[j] + W1[k * DINn + 1] * W3[Hn + j]);
    int chunk = k >> 5, kk = k & 31;
    int off = chunk * 8192 + j * 32 + kk;
    __half whi = __float2half_rn(w2);
    g_W16[off] = whi;
    g_W16[65536 + off]  = __float2half_rn(w2 - __half2float(whi));
    g_W16[131072 + off] = __float2half_rn(mm);
}

// ---------------------------------------------------------------------------
// SMEM layout (byte offsets)
// ---------------------------------------------------------------------------
#define SM_C0    0
#define SM_C1    1024
#define SM_CT    2048
#define SM_CS    3072
#define SM_BASE  4096
#define SM_B2    5120
#define SM_W30   6144
#define SM_W31   7168
#define SM_X0    8192
#define SM_X1    8704
#define SM_SS    9216
#define SM_AH    9728          // 128 x 528 B = 67584 (h1 fp16, full-width)
#define SM_PART  SM_AH         // aliased: [3][4][128] f32 (epilogue only; AH dead)
#define SM_AG    77312         // 67584 (g1 fp16 full-width; reused for D fp16)
#define SM_B     144896        // 2 bufs x 40960
#define SM_TOTAL 226816

#define BBUF_SZ  40960
#define A_STRIDE 528
#define B_STRIDE 80

// ---------------------------------------------------------------------------
// Main fused CNF kernel.
// Per step: div GEMM first (G.M, 1 term) with layer-1 slices interleaved;
// accD spilled fp16 into dead G region; velocity GEMM (H.(W2hi+W2lo), 2 terms,
// A fragments shared); single fused epilogue computes v AND dv.
// ---------------------------------------------------------------------------
__global__ void __launch_bounds__(NTHREADS, 1)
cnf_kernel(const float* __restrict__ x,
           const float* __restrict__ b2,
           const float* __restrict__ W3,
           const float* __restrict__ b3,
           const float* __restrict__ osc,
           float* __restrict__ out,
           int out_size) {
    extern __shared__ char smem[];
    float* sf = reinterpret_cast<float*>(smem);
    const uint32_t sb = smem_u32(smem);

    const int tid  = threadIdx.x;
    const int wid  = tid >> 5;
    const int lane = tid & 31;
    const int gp0  = blockIdx.x * PPC;
    const int bidx = gp0 >> 11;

    // constants -> smem
    sf[(SM_C0 >> 2) + tid]   = g_c0[tid];
    sf[(SM_C1 >> 2) + tid]   = g_c1[tid];
    sf[(SM_CT >> 2) + tid]   = g_ct[tid];
    sf[(SM_CS >> 2) + tid]   = g_csum[tid];
    sf[(SM_BASE >> 2) + tid] = g_base[bidx * Hn + tid];
    sf[(SM_B2 >> 2) + tid]   = b2[tid];
    sf[(SM_W30 >> 2) + tid]  = W3[tid];
    sf[(SM_W31 >> 2) + tid]  = W3[Hn + tid];
    if (tid < PPC) {
        int gp = gp0 + tid;
        sf[(SM_X0 >> 2) + tid] = x[gp * 2 + 0];
        sf[(SM_X1 >> 2) + tid] = x[gp * 2 + 1];
        sf[(SM_SS >> 2) + tid] = 0.f;
    }

    // B-tile streamer: tile q; idx<8 -> M chunk (16KB); idx>=8 -> W2hi+W2lo (32KB)
    auto issue_b = [&](int q) {
        int idx = q & 15;
        int ch  = q & 7;
        uint32_t dst = sb + SM_B + (uint32_t)(q & 1) * BBUF_SZ;
        if (idx < 8) {
            const __half* src = g_W16 + 131072 + ch * 8192;
#pragma unroll
            for (int i = 0; i < 4; ++i) {
                int t = i * NTHREADS + tid;
                cp16(dst + (uint32_t)(t >> 2) * B_STRIDE + (uint32_t)(t & 3) * 16u,
                     src + t * 8);
            }
        } else {
            const __half* srcH = g_W16 + ch * 8192;
            const __half* srcL = g_W16 + 65536 + ch * 8192;
#pragma unroll
            for (int i = 0; i < 4; ++i) {
                int t = i * NTHREADS + tid;
                uint32_t off = (uint32_t)(t >> 2) * B_STRIDE + (uint32_t)(t & 3) * 16u;
                cp16(dst + off, srcH + t * 8);
                cp16(dst + 20480u + off, srcL + t * 8);
            }
        }
        CP_COMMIT();
    };

    issue_b(0);          // first div tile in flight before anything else
    __syncthreads();

    const float scale = __ldg(osc);
    const float dt  = 1.0f / (float)STEPSn;
    const float b30 = __ldg(b3), b31 = __ldg(b3 + 1);

    // layer-1 mapping: 128 points x 2 k-halves of 16 per slice
    const int p_mine = tid >> 1;
    const int khalf  = tid & 1;
    // mma warp tiling: 2 (M) x 4 (N), 64x64 warp tiles
    const int warp_m = wid >> 2;
    const int warp_n = wid & 3;
    const int m0w = warp_m * 64;
    const int n0w = warp_n * 64;
    const int grp = lane >> 2, tig = lane & 3;
    const uint32_t aoffG = (uint32_t)(lane & 15) * A_STRIDE + ((uint32_t)(lane >> 4) << 4);
    const uint32_t boff = ((uint32_t)((lane & 7) + ((lane >> 4) << 3))) * B_STRIDE
                        + (((uint32_t)(lane >> 3) & 1u) << 4);

    const float* c0s = sf + (SM_C0 >> 2);
    const float* c1s = sf + (SM_C1 >> 2);
    const float* cts = sf + (SM_CT >> 2);
    const float* css = sf + (SM_CS >> 2);
    const float* bas = sf + (SM_BASE >> 2);
    const float* b2s = sf + (SM_B2 >> 2);
    const float* w30s = sf + (SM_W30 >> 2);
    const float* w31s = sf + (SM_W31 >> 2);
    float* part = sf + (SM_PART >> 2);

#pragma unroll 1
    for (int step = 0; step < STEPSn; ++step) {
        const float tcur = dt * (float)step;
        const float px0 = sf[(SM_X0 >> 2) + p_mine];
        const float px1 = sf[(SM_X1 >> 2) + p_mine];
        const float psv = sf[(SM_SS >> 2) + p_mine];

        // layer-1 k-slice: tanh once, H + G fp16 to final full-width locations
        auto layer1_slice = [&](int s) {
            const int kb = s * 32 + khalf * 16;
#pragma unroll
            for (int i = 0; i < 16; i += 2) {
                int k = kb + i;
                float2 b_ = *reinterpret_cast<const float2*>(bas + k);
                float2 t_ = *reinterpret_cast<const float2*>(cts + k);
                float2 s_ = *reinterpret_cast<const float2*>(css + k);
                float2 a_ = *reinterpret_cast<const float2*>(c0s + k);
                float2 d_ = *reinterpret_cast<const float2*>(c1s + k);
                float u0 = b_.x + tcur * t_.x + psv * s_.x + px0 * a_.x + px1 * d_.x;
                float u1 = b_.y + tcur * t_.y + psv * s_.y + px0 * a_.y + px1 * d_.y;
                float h0 = ftanh(u0), h1 = ftanh(u1);
                uint32_t o = (uint32_t)p_mine * A_STRIDE + (uint32_t)k * 2u;
                *reinterpret_cast<__half2*>(smem + SM_AH + o) =
                    __floats2half2_rn(h0, h1);
                *reinterpret_cast<__half2*>(smem + SM_AG + o) =
                    __floats2half2_rn(1.f - h0 * h0, 1.f - h1 * h1);
            }
        };

        layer1_slice(0);

        // ================= pass A: divergence GEMM (G . M) =================
        {
            float accD[4][8][4];
#pragma unroll
            for (int mi = 0; mi < 4; ++mi)
#pragma unroll
                for (int ni = 0; ni < 8; ++ni)
#pragma unroll
                    for (int q2 = 0; q2 < 4; ++q2) accD[mi][ni][q2] = 0.f;

#pragma unroll 1
            for (int c = 0; c < NCHUNK; ++c) {
                const int q = step * 16 + c;
                CP_WAIT0();
                __syncthreads();
                issue_b(q + 1);

                const uint32_t bb = sb + SM_B + (uint32_t)(q & 1) * BBUF_SZ;
                const uint32_t ab = sb + SM_AG + (uint32_t)c * 64u;
#pragma unroll
                for (int ks = 0; ks < 2; ++ks) {
                    uint32_t a[4][4];
#pragma unroll
                    for (int mi = 0; mi < 4; ++mi) {
                        uint32_t ad = ab + (uint32_t)(m0w + mi * 16) * A_STRIDE
                                    + (uint32_t)ks * 32u + aoffG;
                        ldsm4(a[mi][0], a[mi][1], a[mi][2], a[mi][3], ad);
                    }
#pragma unroll
                    for (int ng = 0; ng < 4; ++ng) {
                        uint32_t r0, r1, r2, r3;
                        uint32_t bd = bb + (uint32_t)(n0w + ng * 16) * B_STRIDE
                                    + (uint32_t)ks * 32u + boff;
                        ldsm4(r0, r1, r2, r3, bd);
#pragma unroll
                        for (int mi = 0; mi < 4; ++mi) {
                            mma16816(accD[mi][ng * 2],     a[mi], r0, r1);
                            mma16816(accD[mi][ng * 2 + 1], a[mi], r2, r3);
                        }
                    }
                }
                // layer-1 for the NEXT k-slice hides under this chunk's MMA
                if (c + 1 < NCHUNK) layer1_slice(c + 1);
            }

            __syncthreads();   // all G reads done -> safe to overwrite AG with D

            // spill accD (fp16) into the dead G region; same thread reloads it
#pragma unroll
            for (int mi = 0; mi < 4; ++mi) {
                int p0 = m0w + mi * 16 + grp;
#pragma unroll
                for (int ni = 0; ni < 8; ++ni) {
                    int j0 = n0w + ni * 8 + tig * 2;
                    float* cD = accD[mi][ni];
                    *reinterpret_cast<__half2*>(
                        smem + SM_AG + (uint32_t)p0 * A_STRIDE + (uint32_t)j0 * 2u) =
                        __floats2half2_rn(cD[0], cD[1]);
                    *reinterpret_cast<__half2*>(
                        smem + SM_AG + (uint32_t)(p0 + 8) * A_STRIDE + (uint32_t)j0 * 2u) =
                        __floats2half2_rn(cD[2], cD[3]);
                }
            }
        }

        // ================= pass B: velocity GEMM (H . (W2hi + W2lo)) =======
        float accA[4][8][4];
#pragma unroll
        for (int mi = 0; mi < 4; ++mi)
#pragma unroll
            for (int ni = 0; ni < 8; ++ni)
#pragma unroll
                for (int q2 = 0; q2 < 4; ++q2) accA[mi][ni][q2] = 0.f;

#pragma unroll 1
        for (int c = 0; c < NCHUNK; ++c) {
            const int q = step * 16 + 8 + c;
            CP_WAIT0();
            __syncthreads();
            if (q + 1 < NTILES) issue_b(q + 1);

            const uint32_t bb = sb + SM_B + (uint32_t)(q & 1) * BBUF_SZ;
            const uint32_t ab = sb + SM_AH + (uint32_t)c * 64u;
#pragma unroll
            for (int ks = 0; ks < 2; ++ks) {
                uint32_t a[4][4];
#pragma unroll
                for (int mi = 0; mi < 4; ++mi) {
                    uint32_t ad = ab + (uint32_t)(m0w + mi * 16) * A_STRIDE
                                + (uint32_t)ks * 32u + aoffG;
                    ldsm4(a[mi][0], a[mi][1], a[mi][2], a[mi][3], ad);
                }
                // hi term
#pragma unroll
                for (int ng = 0; ng < 4; ++ng) {
                    uint32_t r0, r1, r2, r3;
                    uint32_t bd = bb + (uint32_t)(n0w + ng * 16) * B_STRIDE
                                + (uint32_t)ks * 32u + boff;
                    ldsm4(r0, r1, r2, r3, bd);
#pragma unroll
                    for (int mi = 0; mi < 4; ++mi) {
                        mma16816(accA[mi][ng * 2],     a[mi], r0, r1);
                        mma16816(accA[mi][ng * 2 + 1], a[mi], r2, r3);
                    }
                }
                // lo term (same A fragments)
#pragma unroll
                for (int ng = 0; ng < 4; ++ng) {
                    uint32_t r0, r1, r2, r3;
                    uint32_t bd = bb + 20480u + (uint32_t)(n0w + ng * 16) * B_STRIDE
                                + (uint32_t)ks * 32u + boff;
                    ldsm4(r0, r1, r2, r3, bd);
#pragma unroll
                    for (int mi = 0; mi < 4; ++mi) {
                        mma16816(accA[mi][ng * 2],     a[mi], r0, r1);
                        mma16816(accA[mi][ng * 2 + 1], a[mi], r2, r3);
                    }
                }
            }
        }

        // ---- fused epilogue: h2, v partials AND dv partials (D from smem) ----
        {
            float v0p[8], v1p[8], dvp[8];
#pragma unroll
            for (int i = 0; i < 8; ++i) { v0p[i] = 0.f; v1p[i] = 0.f; dvp[i] = 0.f; }
#pragma unroll
            for (int mi = 0; mi < 4; ++mi) {
                int p0 = m0w + mi * 16 + grp;
#pragma unroll
                for (int ni = 0; ni < 8; ++ni) {
                    int j0 = n0w + ni * 8 + tig * 2;
                    float* cA = accA[mi][ni];
                    float h00 = ftanh(cA[0] + b2s[j0]);
                    float h01 = ftanh(cA[1] + b2s[j0 + 1]);
                    float h10 = ftanh(cA[2] + b2s[j0]);
                    float h11 = ftanh(cA[3] + b2s[j0 + 1]);
                    v0p[2*mi]   += w30s[j0] * h00 + w30s[j0+1] * h01;
                    v0p[2*mi+1] += w30s[j0] * h10 + w30s[j0+1] * h11;
                    v1p[2*mi]   += w31s[j0] * h00 + w31s[j0+1] * h01;
                    v1p[2*mi+1] += w31s[j0] * h10 + w31s[j0+1] * h11;
                    float2 Da = __half22float2(*reinterpret_cast<__half2*>(
                        smem + SM_AG + (uint32_t)p0 * A_STRIDE + (uint32_t)j0 * 2u));
                    float2 Db = __half22float2(*reinterpret_cast<__half2*>(
                        smem + SM_AG + (uint32_t)(p0 + 8) * A_STRIDE + (uint32_t)j0 * 2u));
                    dvp[2*mi]   += (1.f - h00 * h00) * Da.x + (1.f - h01 * h01) * Da.y;
                    dvp[2*mi+1] += (1.f - h10 * h10) * Db.x + (1.f - h11 * h11) * Db.y;
                }
            }
#pragma unroll
            for (int i = 0; i < 8; ++i) {
                v0p[i] += __shfl_xor_sync(0xffffffffu, v0p[i], 1);
                v0p[i] += __shfl_xor_sync(0xffffffffu, v0p[i], 2);
                v1p[i] += __shfl_xor_sync(0xffffffffu, v1p[i], 1);
                v1p[i] += __shfl_xor_sync(0xffffffffu, v1p[i], 2);
                dvp[i] += __shfl_xor_sync(0xffffffffu, dvp[i], 1);
                dvp[i] += __shfl_xor_sync(0xffffffffu, dvp[i], 2);
            }
            if (tig == 0) {
#pragma unroll
                for (int i = 0; i < 8; ++i) {
                    int p = m0w + (i >> 1) * 16 + grp + (i & 1) * 8;
                    part[0 * 512 + warp_n * 128 + p] = v0p[i];
                    part[1 * 512 + warp_n * 128 + p] = v1p[i];
                    part[2 * 512 + warp_n * 128 + p] = dvp[i];
                }
            }
        }
        __syncthreads();

        // ---- state update ----
        if (tid < PPC) {
            float v0 = b30, v1 = b31, dv = 0.f;
#pragma unroll
            for (int wn = 0; wn < 4; ++wn) {
                v0 += part[0 * 512 + wn * 128 + tid];
                v1 += part[1 * 512 + wn * 128 + tid];
                dv += part[2 * 512 + wn * 128 + tid];
            }
            sf[(SM_X0 >> 2) + tid] += v0 * scale * dt;
            sf[(SM_X1 >> 2) + tid] += v1 * scale * dt;
            sf[(SM_SS >> 2) + tid] += dv * scale * dt;
        }
        __syncthreads();
    }

    if (tid < PPC) {
        int gp = gp0 + tid;
        out[gp * 2 + 0] = sf[(SM_X0 >> 2) + tid];
        out[gp * 2 + 1] = sf[(SM_X1 >> 2) + tid];
        if (out_size >= NPTS * PDn + NPTS)
            out[NPTS * PDn + gp] = sf[(SM_SS >> 2) + tid];
    }
}

// ---------------------------------------------------------------------------
// kernel_launch
// Inputs (metadata order): x, z, W1, b1, W2, b2, W3, b3, out_scale
// ---------------------------------------------------------------------------
extern "C" void kernel_launch(void* const* d_in, const int* in_sizes, int n_in,
                              void* d_out, int out_size) {
    const float* x   = (const float*)d_in[0];
    const float* z   = (const float*)d_in[1];
    const float* W1  = (const float*)d_in[2];
    const float* b1  = (const float*)d_in[3];
    const float* W2  = (const float*)d_in[4];
    const float* b2  = (const float*)d_in[5];
    const float* W3  = (const float*)d_in[6];
    const float* b3  = (const float*)d_in[7];
    const float* osc = (const float*)d_in[8];
    float* out = (float*)d_out;

    precomp_aux<<<Bn, 256>>>(W1, b1, z);
    precomp_w<<<256, 256>>>(W1, W2, W3);

    cudaFuncSetAttribute(cnf_kernel, cudaFuncAttributeMaxDynamicSharedMemorySize,
                         SM_TOTAL);
    cnf_kernel<<<NCTA, NTHREADS, SM_TOTAL>>>(x, b2, W3, b3, osc, out, out_size);
}

// round 11
// speedup vs baseline: 1.3775x; 1.3775x over previous
#include <cuda_runtime.h>
#include <cuda_fp16.h>
#include <cstdint>

// ---------------------------------------------------------------------------
// Problem constants
// ---------------------------------------------------------------------------
#define Bn     32
#define Nn     2048
#define PDn    2
#define LATn   128
#define Hn     256
#define STEPSn 5
#define DINn   131
#define NPTS   (Bn * Nn)         // 65536
#define PPC    128               // points per CTA (= GEMM M)
#define NCTA   (NPTS / PPC)      // 512
#define KCH    64                // K-chunk
#define NCHUNK (Hn / KCH)        // 4
#define NTHREADS 256
#define NTILES (STEPSn * 2 * NCHUNK)   // 40 B-tiles over the whole kernel

// ---------------------------------------------------------------------------
// Device globals
// ---------------------------------------------------------------------------
// fp16 weights, chunk-major: [matrix(2: W2, M)][chunk(4)][j=256][kk=64]
__device__ __align__(16) __half g_W16[2 * NCHUNK * Hn * KCH];
__device__ __align__(16) float g_base[Bn * Hn];
__device__ __align__(16) float g_c0[Hn], g_c1[Hn], g_ct[Hn], g_csum[Hn];

__device__ __forceinline__ float ftanh(float x) {
    float e = __expf(2.0f * x);
    return 1.0f - __fdividef(2.0f, e + 1.0f);
}
__device__ __forceinline__ uint32_t smem_u32(const void* p) {
    uint32_t a;
    asm("{ .reg .u64 t; cvta.to.shared.u64 t, %1; cvt.u32.u64 %0, t; }"
        : "=r"(a) : "l"(p));
    return a;
}
__device__ __forceinline__ void ldsm4(uint32_t& r0, uint32_t& r1,
                                      uint32_t& r2, uint32_t& r3, uint32_t addr) {
    asm volatile("ldmatrix.sync.aligned.m8n8.x4.shared.b16 {%0,%1,%2,%3}, [%4];"
                 : "=r"(r0), "=r"(r1), "=r"(r2), "=r"(r3) : "r"(addr));
}
__device__ __forceinline__ void mma16816(float* d, const uint32_t* a,
                                         uint32_t b0, uint32_t b1) {
    asm volatile(
        "mma.sync.aligned.m16n8k16.row.col.f32.f16.f16.f32 "
        "{%0,%1,%2,%3},{%4,%5,%6,%7},{%8,%9},{%0,%1,%2,%3};"
        : "+f"(d[0]), "+f"(d[1]), "+f"(d[2]), "+f"(d[3])
        : "r"(a[0]), "r"(a[1]), "r"(a[2]), "r"(a[3]), "r"(b0), "r"(b1));
}
__device__ __forceinline__ void cp16(uint32_t dst, const void* src) {
    asm volatile("cp.async.cg.shared.global [%0], [%1], 16;"
                 :: "r"(dst), "l"(src));
}
#define CP_COMMIT() asm volatile("cp.async.commit_group;" ::: "memory")
#define CP_WAIT0()  asm volatile("cp.async.wait_group 0;" ::: "memory")

// ---------------------------------------------------------------------------
// Precompute 1: per-row W1 decomposition + per-batch base vectors
// ---------------------------------------------------------------------------
__global__ void precomp_aux(const float* __restrict__ W1,
                            const float* __restrict__ b1,
                            const float* __restrict__ z) {
    int k = threadIdx.x;
    int b = blockIdx.x;
    const float* row = W1 + k * DINn;
    float d = b1[k];
    const float* zb = z + b * LATn;
#pragma unroll 16
    for (int l = 0; l < LATn; ++l) d += row[3 + l] * zb[l];
    g_base[b * Hn + k] = d;
    if (b == 0) {
        float s = 0.f;
#pragma unroll 16
        for (int l = 0; l < LATn; ++l) s += row[3 + l];
        g_c0[k] = row[0]; g_c1[k] = row[1]; g_ct[k] = row[2]; g_csum[k] = s;
    }
}

// ---------------------------------------------------------------------------
// Precompute 2: W2 and fused divergence matrix M -> fp16, chunk-major
// ---------------------------------------------------------------------------
__global__ void precomp_w(const float* __restrict__ W1,
                          const float* __restrict__ W2,
                          const float* __restrict__ W3) {
    int j = blockIdx.x;   // 256
    int k = threadIdx.x;  // 256
    float w2 = W2[j * Hn + k];
    float mm = w2 * (W1[k * DINn] * W3[j] + W1[k * DINn + 1] * W3[Hn + j]);
    int chunk = k >> 6, kk = k & 63;
    int idx = chunk * (Hn * KCH) + j * KCH + kk;
    g_W16[idx] = __float2half_rn(w2);
    g_W16[NCHUNK * Hn * KCH + idx] = __float2half_rn(mm);
}

// ---------------------------------------------------------------------------
// SMEM layout (byte offsets)
// ---------------------------------------------------------------------------
#define SM_C0    0
#define SM_C1    1024
#define SM_CT    2048
#define SM_CS    3072
#define SM_BASE  4096
#define SM_B2    5120
#define SM_W30   6144
#define SM_W31   7168
#define SM_X0    8192
#define SM_X1    8704
#define SM_SS    9216
#define SM_PART  9728          // [3][4][128] f32 = 6144
#define SM_AH    16384         // 2 bufs x (128 x 72 halfs = 18432) = 36864
#define SM_B     53248         // 2 bufs x (256 x 72 halfs = 36864) = 73728
#define SM_AG    126976        // 128 x 264 halfs = 67584 (g1 full-width)
#define SM_TOTAL 194560

#define ABUF_SZ  18432
#define BBUF_SZ  36864
#define AG_STRIDE 528

// ---------------------------------------------------------------------------
// Main fused CNF kernel: tanh ONCE per step.
// pass0 = velocity GEMM, SINGLE term (h fp16 . W2 fp16), A-tile ping-pong so
//         layer-1(c+1) overlaps MMA(c) with one barrier per chunk.
// pass1 = divergence GEMM, single term (g1 full-width . M), no bottom syncs.
// g2 (layer-2 derivative) carried in registers between the two epilogues.
// ---------------------------------------------------------------------------
__global__ void __launch_bounds__(NTHREADS, 1)
cnf_kernel(const float* __restrict__ x,
           const float* __restrict__ b2,
           const float* __restrict__ W3,
           const float* __restrict__ b3,
           const float* __restrict__ osc,
           float* __restrict__ out,
           int out_size) {
    extern __shared__ char smem[];
    float* sf = reinterpret_cast<float*>(smem);
    const uint32_t sb = smem_u32(smem);

    const int tid  = threadIdx.x;
    const int wid  = tid >> 5;
    const int lane = tid & 31;
    const int gp0  = blockIdx.x * PPC;
    const int bidx = gp0 >> 11;

    // load constants into smem
    sf[(SM_C0 >> 2) + tid]   = g_c0[tid];
    sf[(SM_C1 >> 2) + tid]   = g_c1[tid];
    sf[(SM_CT >> 2) + tid]   = g_ct[tid];
    sf[(SM_CS >> 2) + tid]   = g_csum[tid];
    sf[(SM_BASE >> 2) + tid] = g_base[bidx * Hn + tid];
    sf[(SM_B2 >> 2) + tid]   = b2[tid];
    sf[(SM_W30 >> 2) + tid]  = W3[tid];
    sf[(SM_W31 >> 2) + tid]  = W3[Hn + tid];
    if (tid < PPC) {
        int gp = gp0 + tid;
        sf[(SM_X0 >> 2) + tid] = x[gp * 2 + 0];
        sf[(SM_X1 >> 2) + tid] = x[gp * 2 + 1];
        sf[(SM_SS >> 2) + tid] = 0.f;
    }

// issue B-tile q (q in [0,NTILES)) into buffer (q&1) via cp.async
#define ISSUE_B(q) do {                                                    \
        int _q8 = (q) & 7;                                                 \
        int _img = (_q8 >= NCHUNK) ? 1 : 0;                                \
        int _ch  = (q) & 3;                                                \
        const __half* _src = g_W16 + (_img * NCHUNK + _ch) * (Hn * KCH);   \
        uint32_t _dst = sb + SM_B + (uint32_t)((q) & 1) * BBUF_SZ;         \
        _Pragma("unroll")                                                  \
        for (int _i = 0; _i < 8; ++_i) {                                   \
            int _idx = _i * NTHREADS + tid;                                \
            int _j = _idx >> 3, _kb = _idx & 7;                            \
            cp16(_dst + (uint32_t)_j * 144u + (uint32_t)_kb * 16u,         \
                 _src + _idx * 8);                                         \
        }                                                                  \
        CP_COMMIT();                                                       \
    } while (0)

    // prologue: first B tile in flight before anything else
    ISSUE_B(0);
    __syncthreads();

    const float scale = __ldg(osc);
    const float dt  = 1.0f / (float)STEPSn;
    const float b30 = __ldg(b3), b31 = __ldg(b3 + 1);

    // layer-1 mapping
    const int p_mine = tid >> 1;
    const int khalf  = tid & 1;
    // mma warp tiling: 2 (M) x 4 (N), 64x64 warp tiles
    const int warp_m = wid >> 2;
    const int warp_n = wid & 3;
    const int m0w = warp_m * 64;
    const int n0w = warp_n * 64;
    const int grp = lane >> 2, tig = lane & 3;
    const uint32_t aoff  = (uint32_t)(lane & 15) * 144u + ((uint32_t)(lane >> 4) << 4);
    const uint32_t aoffG = (uint32_t)(lane & 15) * AG_STRIDE + ((uint32_t)(lane >> 4) << 4);
    const uint32_t boff = ((uint32_t)((lane & 7) + ((lane >> 4) << 3))) * 144u
                        + (((uint32_t)(lane >> 3) & 1u) << 4);

    const float* c0s = sf + (SM_C0 >> 2);
    const float* c1s = sf + (SM_C1 >> 2);
    const float* cts = sf + (SM_CT >> 2);
    const float* css = sf + (SM_CS >> 2);
    const float* bas = sf + (SM_BASE >> 2);
    const float* b2s = sf + (SM_B2 >> 2);
    const float* w30s = sf + (SM_W30 >> 2);
    const float* w31s = sf + (SM_W31 >> 2);
    float* part = sf + (SM_PART >> 2);

    uint32_t g2a[4][8], g2b[4][8];   // layer-2 derivative stash (packed half2)

#pragma unroll 1
    for (int step = 0; step < STEPSn; ++step) {
        const float tcur = dt * (float)step;
        const float px0 = sf[(SM_X0 >> 2) + p_mine];
        const float px1 = sf[(SM_X1 >> 2) + p_mine];
        const float psv = sf[(SM_SS >> 2) + p_mine];

        // layer-1 k-slice for chunk c: tanh once; h fp16 -> A buf (c&1),
        // g1 fp16 -> full-width AG at final column position.
        auto layer1 = [&](int c) {
            const int kkb = khalf * 32;
            const uint32_t abuf = sb; (void)abuf;
            const uint32_t aw = (uint32_t)(c & 1) * ABUF_SZ;
#pragma unroll
            for (int kk2 = 0; kk2 < 32; kk2 += 2) {
                int kk = kkb + kk2;
                int k = c * KCH + kk;
                float u0 = bas[k] + tcur * cts[k] + psv * css[k]
                         + px0 * c0s[k] + px1 * c1s[k];
                float u1 = bas[k+1] + tcur * cts[k+1] + psv * css[k+1]
                         + px0 * c0s[k+1] + px1 * c1s[k+1];
                float h0 = ftanh(u0), h1 = ftanh(u1);
                uint32_t o = aw + (uint32_t)p_mine * 144u + (uint32_t)kk * 2u;
                *reinterpret_cast<__half2*>(smem + SM_AH + o) =
                    __floats2half2_rn(h0, h1);
                uint32_t og = (uint32_t)p_mine * AG_STRIDE + (uint32_t)k * 2u;
                *reinterpret_cast<__half2*>(smem + SM_AG + og) =
                    __floats2half2_rn(1.f - h0 * h0, 1.f - h1 * h1);
            }
        };

        float acc[4][8][4];
#pragma unroll
        for (int mi = 0; mi < 4; ++mi)
#pragma unroll
            for (int ni = 0; ni < 8; ++ni)
#pragma unroll
                for (int q = 0; q < 4; ++q) acc[mi][ni][q] = 0.f;

        // ============ pass 0: velocity GEMM (h . W2, single term) ==========
        layer1(0);
#pragma unroll 1
        for (int chunk = 0; chunk < NCHUNK; ++chunk) {
            const int q = step * 8 + chunk;

            CP_WAIT0();          // B(q) landed
            __syncthreads();     // A(chunk) stores + B visible; prev reads done
            ISSUE_B(q + 1);      // hide next B under MMA(q)

            const uint32_t bb = sb + SM_B + (uint32_t)(q & 1) * BBUF_SZ;
            const uint32_t ab = sb + SM_AH + (uint32_t)(chunk & 1) * ABUF_SZ;
#pragma unroll
            for (int ks = 0; ks < 4; ++ks) {
                uint32_t a[4][4];
#pragma unroll
                for (int mi = 0; mi < 4; ++mi) {
                    uint32_t ad = ab + (uint32_t)(m0w + mi * 16) * 144u
                                + (uint32_t)ks * 32u + aoff;
                    ldsm4(a[mi][0], a[mi][1], a[mi][2], a[mi][3], ad);
                }
#pragma unroll
                for (int ng = 0; ng < 4; ++ng) {
                    uint32_t r0, r1, r2, r3;
                    uint32_t bd = bb + (uint32_t)(n0w + ng * 16) * 144u
                                + (uint32_t)ks * 32u + boff;
                    ldsm4(r0, r1, r2, r3, bd);
#pragma unroll
                    for (int mi = 0; mi < 4; ++mi) {
                        mma16816(acc[mi][ng * 2],     a[mi], r0, r1);
                        mma16816(acc[mi][ng * 2 + 1], a[mi], r2, r3);
                    }
                }
            }
            // layer-1 for chunk+1 into the OTHER A buffer: no sync needed,
            // next iteration's top barrier publishes it before MMA(chunk+1).
            if (chunk + 1 < NCHUNK) layer1(chunk + 1);
        }

        // ---- epilogue 0: h2, v partials; g2 -> registers ----
        {
            float v0p[8], v1p[8];
#pragma unroll
            for (int i = 0; i < 8; ++i) { v0p[i] = 0.f; v1p[i] = 0.f; }
#pragma unroll
            for (int mi = 0; mi < 4; ++mi) {
#pragma unroll
                for (int ni = 0; ni < 8; ++ni) {
                    int j0 = n0w + ni * 8 + tig * 2;
                    float* c = acc[mi][ni];
                    float h00 = ftanh(c[0] + b2s[j0]);
                    float h01 = ftanh(c[1] + b2s[j0 + 1]);
                    float h10 = ftanh(c[2] + b2s[j0]);
                    float h11 = ftanh(c[3] + b2s[j0 + 1]);
                    v0p[2*mi]   += w30s[j0] * h00 + w30s[j0+1] * h01;
                    v0p[2*mi+1] += w30s[j0] * h10 + w30s[j0+1] * h11;
                    v1p[2*mi]   += w31s[j0] * h00 + w31s[j0+1] * h01;
                    v1p[2*mi+1] += w31s[j0] * h10 + w31s[j0+1] * h11;
                    __half2 ga = __floats2half2_rn(1.f - h00 * h00, 1.f - h01 * h01);
                    __half2 gb = __floats2half2_rn(1.f - h10 * h10, 1.f - h11 * h11);
                    g2a[mi][ni] = *reinterpret_cast<uint32_t*>(&ga);
                    g2b[mi][ni] = *reinterpret_cast<uint32_t*>(&gb);
                }
            }
#pragma unroll
            for (int i = 0; i < 8; ++i) {
                v0p[i] += __shfl_xor_sync(0xffffffffu, v0p[i], 1);
                v0p[i] += __shfl_xor_sync(0xffffffffu, v0p[i], 2);
                v1p[i] += __shfl_xor_sync(0xffffffffu, v1p[i], 1);
                v1p[i] += __shfl_xor_sync(0xffffffffu, v1p[i], 2);
            }
            if (tig == 0) {
#pragma unroll
                for (int i = 0; i < 8; ++i) {
                    int p = m0w + (i >> 1) * 16 + grp + (i & 1) * 8;
                    part[0 * 512 + warp_n * 128 + p] = v0p[i];
                    part[1 * 512 + warp_n * 128 + p] = v1p[i];
                }
            }
        }

        // ============ pass 1: divergence GEMM (g1 . M, single term) ========
#pragma unroll
        for (int mi = 0; mi < 4; ++mi)
#pragma unroll
            for (int ni = 0; ni < 8; ++ni)
#pragma unroll
                for (int q = 0; q < 4; ++q) acc[mi][ni][q] = 0.f;

#pragma unroll 1
        for (int chunk = 0; chunk < NCHUNK; ++chunk) {
            const int q = step * 8 + 4 + chunk;

            CP_WAIT0();
            __syncthreads();
            if (q + 1 < NTILES) ISSUE_B(q + 1);

            const uint32_t bb = sb + SM_B + (uint32_t)(q & 1) * BBUF_SZ;
            const uint32_t ab = sb + SM_AG + (uint32_t)chunk * 128u;
#pragma unroll
            for (int ks = 0; ks < 4; ++ks) {
                uint32_t a[4][4];
#pragma unroll
                for (int mi = 0; mi < 4; ++mi) {
                    uint32_t ad = ab + (uint32_t)(m0w + mi * 16) * AG_STRIDE
                                + (uint32_t)ks * 32u + aoffG;
                    ldsm4(a[mi][0], a[mi][1], a[mi][2], a[mi][3], ad);
                }
#pragma unroll
                for (int ng = 0; ng < 4; ++ng) {
                    uint32_t r0, r1, r2, r3;
                    uint32_t bd = bb + (uint32_t)(n0w + ng * 16) * 144u
                                + (uint32_t)ks * 32u + boff;
                    ldsm4(r0, r1, r2, r3, bd);
#pragma unroll
                    for (int mi = 0; mi < 4; ++mi) {
                        mma16816(acc[mi][ng * 2],     a[mi], r0, r1);
                        mma16816(acc[mi][ng * 2 + 1], a[mi], r2, r3);
                    }
                }
            }
            // no bottom sync: AG is read-only; B buffers guarded by top sync
        }

        // ---- epilogue 1: dv partials from g2 registers ----
        {
            float dvp[8];
#pragma unroll
            for (int i = 0; i < 8; ++i) dvp[i] = 0.f;
#pragma unroll
            for (int mi = 0; mi < 4; ++mi) {
#pragma unroll
                for (int ni = 0; ni < 8; ++ni) {
                    float* c = acc[mi][ni];
                    float2 ga = __half22float2(
                        *reinterpret_cast<__half2*>(&g2a[mi][ni]));
                    float2 gb = __half22float2(
                        *reinterpret_cast<__half2*>(&g2b[mi][ni]));
                    dvp[2*mi]   += ga.x * c[0] + ga.y * c[1];
                    dvp[2*mi+1] += gb.x * c[2] + gb.y * c[3];
                }
            }
#pragma unroll
            for (int i = 0; i < 8; ++i) {
                dvp[i] += __shfl_xor_sync(0xffffffffu, dvp[i], 1);
                dvp[i] += __shfl_xor_sync(0xffffffffu, dvp[i], 2);
            }
            if (tig == 0) {
#pragma unroll
                for (int i = 0; i < 8; ++i) {
                    int p = m0w + (i >> 1) * 16 + grp + (i & 1) * 8;
                    part[2 * 512 + warp_n * 128 + p] = dvp[i];
                }
            }
        }
        __syncthreads();

        // ---- state update ----
        if (tid < PPC) {
            float v0 = b30, v1 = b31, dv = 0.f;
#pragma unroll
            for (int wn = 0; wn < 4; ++wn) {
                v0 += part[0 * 512 + wn * 128 + tid];
                v1 += part[1 * 512 + wn * 128 + tid];
                dv += part[2 * 512 + wn * 128 + tid];
            }
            sf[(SM_X0 >> 2) + tid] += v0 * scale * dt;
            sf[(SM_X1 >> 2) + tid] += v1 * scale * dt;
            sf[(SM_SS >> 2) + tid] += dv * scale * dt;
        }
        __syncthreads();
    }

    if (tid < PPC) {
        int gp = gp0 + tid;
        out[gp * 2 + 0] = sf[(SM_X0 >> 2) + tid];
        out[gp * 2 + 1] = sf[(SM_X1 >> 2) + tid];
        if (out_size >= NPTS * PDn + NPTS)
            out[NPTS * PDn + gp] = sf[(SM_SS >> 2) + tid];
    }
#undef ISSUE_B
}

// ---------------------------------------------------------------------------
// kernel_launch
// Inputs (metadata order): x, z, W1, b1, W2, b2, W3, b3, out_scale
// ---------------------------------------------------------------------------
extern "C" void kernel_launch(void* const* d_in, const int* in_sizes, int n_in,
                              void* d_out, int out_size) {
    const float* x   = (const float*)d_in[0];
    const float* z   = (const float*)d_in[1];
    const float* W1  = (const float*)d_in[2];
    const float* b1  = (const float*)d_in[3];
    const float* W2  = (const float*)d_in[4];
    const float* b2  = (const float*)d_in[5];
    const float* W3  = (const float*)d_in[6];
    const float* b3  = (const float*)d_in[7];
    const float* osc = (const float*)d_in[8];
    float* out = (float*)d_out;

    precomp_aux<<<Bn, 256>>>(W1, b1, z);
    precomp_w<<<256, 256>>>(W1, W2, W3);

    cudaFuncSetAttribute(cnf_kernel, cudaFuncAttributeMaxDynamicSharedMemorySize,
                         SM_TOTAL);
    cnf_kernel<<<NCTA, NTHREADS, SM_TOTAL>>>(x, b2, W3, b3, osc, out, out_size);
}